// round 5
// baseline (speedup 1.0000x reference)
#include <cuda_runtime.h>

#define NN 204800
#define EE 1638400
#define BB 4096
#define KTOP 10
#define NPG 50

// ---------------- scratch (no allocation allowed) ----------------
__device__ float g_dinv[NN];
__device__ int   g_cnt[NN];
__device__ int   g_off[NN];
__device__ int   g_cur[NN];
__device__ int   g_bsum[200];
__device__ int   g_src[EE];
__device__ float g_coef[EE];
__device__ float g_h[(size_t)NN * 64];       // GEMM output per layer
__device__ float g_feat[(size_t)NN * 192];   // x1 | x2 | x3 concat
__device__ float g_key[NN];                  // per-node max feature
__device__ int   g_sel[BB * KTOP];           // selected node per (graph, rank)
__device__ float g_pooled[(size_t)BB * KTOP * 192];

// ---------------- degree / CSR build ----------------
__global__ void k_init() {
    int i = blockIdx.x * 256 + threadIdx.x;
    g_cnt[i] = 0; g_cur[i] = 0;
}

__global__ void k_count(const int* __restrict__ col) {
    int e = blockIdx.x * 256 + threadIdx.x;
    atomicAdd(&g_cnt[col[e]], 1);
}

__global__ void k_scan_blk() {
    __shared__ int sh[1024];
    int t = threadIdx.x, i = blockIdx.x * 1024 + t;
    int v = g_cnt[i];
    sh[t] = v; __syncthreads();
    for (int d = 1; d < 1024; d <<= 1) {
        int a = (t >= d) ? sh[t - d] : 0; __syncthreads();
        sh[t] += a; __syncthreads();
    }
    g_off[i] = sh[t] - v;                 // exclusive within block
    if (t == 1023) g_bsum[blockIdx.x] = sh[1023];
}

__global__ void k_scan_top() {
    __shared__ int sh[256];
    int t = threadIdx.x;
    int v = (t < 200) ? g_bsum[t] : 0;
    sh[t] = v; __syncthreads();
    for (int d = 1; d < 256; d <<= 1) {
        int a = (t >= d) ? sh[t - d] : 0; __syncthreads();
        sh[t] += a; __syncthreads();
    }
    if (t < 200) g_bsum[t] = sh[t] - v;   // exclusive block sums
}

__global__ void k_scan_add() {
    int i = blockIdx.x * 1024 + threadIdx.x;
    g_off[i] += g_bsum[blockIdx.x];
}

__global__ void k_dinv() {
    int i = blockIdx.x * 256 + threadIdx.x;
    g_dinv[i] = rsqrtf((float)g_cnt[i] + 1.0f);
}

__global__ void k_scatter(const int* __restrict__ row, const int* __restrict__ col) {
    int e = blockIdx.x * 256 + threadIdx.x;
    int c = col[e], r = row[e];
    int pos = g_off[c] + atomicAdd(&g_cur[c], 1);
    g_src[pos] = r;
    g_coef[pos] = g_dinv[r] * g_dinv[c];
}

// ---------------- GEMM: h = in @ W  (W in shared, shfl broadcast of x row) ----
// one warp per row, lane covers 2 output columns
template<int KDIM>
__global__ void k_gemm(const float* __restrict__ xin, int instride, int inoff,
                       const float* __restrict__ W) {
    __shared__ float Ws[KDIM * 64];
    int t = threadIdx.x;
    for (int i = t; i < KDIM * 64; i += 256) Ws[i] = W[i];
    __syncthreads();
    int lane = t & 31;
    size_t row = (size_t)blockIdx.x * 8 + (t >> 5);
    const float* base = xin ? xin : (const float*)g_feat;
    const float* xp = base + row * instride + inoff;
    float xr[KDIM / 32];
#pragma unroll
    for (int r = 0; r < KDIM / 32; r++) xr[r] = xp[r * 32 + lane];
    float a0 = 0.f, a1 = 0.f;
#pragma unroll
    for (int k = 0; k < KDIM; k++) {
        float xv = __shfl_sync(0xffffffffu, xr[k >> 5], k & 31);
        float2 w = *(const float2*)&Ws[k * 64 + lane * 2];
        a0 = fmaf(xv, w.x, a0);
        a1 = fmaf(xv, w.y, a1);
    }
    *(float2*)&g_h[row * 64 + (size_t)lane * 2] = make_float2(a0, a1);
}

// ---------------- aggregation: one warp per target node, CSR gather ----------
__global__ void k_agg(const float* __restrict__ bias, int outoff) {
    int n = (blockIdx.x * 256 + threadIdx.x) >> 5;
    int lane = threadIdx.x & 31;
    float di = g_dinv[n];
    float s = di * di;
    float2 hv = *(const float2*)&g_h[(size_t)n * 64 + lane * 2];
    float a0 = hv.x * s, a1 = hv.y * s;
    int beg = g_off[n], end = beg + g_cnt[n];
    for (int e = beg; e < end; e++) {
        int src = g_src[e];
        float c = g_coef[e];
        float2 v = *(const float2*)&g_h[(size_t)src * 64 + lane * 2];
        a0 = fmaf(v.x, c, a0);
        a1 = fmaf(v.y, c, a1);
    }
    float t0 = tanhf(a0 + bias[lane * 2]);
    float t1 = tanhf(a1 + bias[lane * 2 + 1]);
    *(float2*)&g_feat[(size_t)n * 192 + outoff + lane * 2] = make_float2(t0, t1);
}

// ---------------- per-node max over 192 features (sort-pool key) ------------
__global__ void k_maxkey() {
    int n = (blockIdx.x * 256 + threadIdx.x) >> 5;
    int lane = threadIdx.x & 31;
    const float* f = g_feat + (size_t)n * 192;
    float m = -3.4e38f;
#pragma unroll
    for (int r = 0; r < 6; r++) m = fmaxf(m, f[r * 32 + lane]);
#pragma unroll
    for (int d = 16; d > 0; d >>= 1) m = fmaxf(m, __shfl_xor_sync(0xffffffffu, m, d));
    if (lane == 0) g_key[n] = m;
}

// ---------------- per-graph top-K selection (key desc, tie: index asc) ------
__global__ void k_select() {
    __shared__ float sk[NPG];
    int g = blockIdx.x, t = threadIdx.x;
    if (t < NPG) sk[t] = g_key[g * NPG + t];
    __syncthreads();
    if (t < NPG) {
        float kv = sk[t];
        int r = 0;
        for (int j = 0; j < NPG; j++) {
            float kj = sk[j];
            r += (int)((kj > kv) || ((kj == kv) && (j < t)));
        }
        if (r < KTOP) g_sel[g * KTOP + r] = g * NPG + t;
    }
}

// ---------------- sort 192 features ascending for selected nodes ------------
// one warp per selected node: bitonic sort of 256 (padded with +inf) via shfl
__global__ void k_sortfeat() {
    int item = (blockIdx.x * 256 + threadIdx.x) >> 5;
    int lane = threadIdx.x & 31;
    int node = g_sel[item];
    const float* f = g_feat + (size_t)node * 192;
    const float INF = __int_as_float(0x7f800000);
    float v[8];
#pragma unroll
    for (int r = 0; r < 8; r++) {
        int idx = r * 32 + lane;
        v[r] = (idx < 192) ? f[idx] : INF;
    }
#pragma unroll
    for (int k = 2; k <= 256; k <<= 1) {
#pragma unroll
        for (int j = 128; j > 0; j >>= 1) {
            if (j >= k) continue;
            if (j < 32) {
#pragma unroll
                for (int r = 0; r < 8; r++) {
                    int idx = r * 32 + lane;
                    float o = __shfl_xor_sync(0xffffffffu, v[r], j);
                    bool up = ((idx & k) == 0);
                    bool lower = ((lane & j) == 0);
                    float mn = fminf(v[r], o), mx = fmaxf(v[r], o);
                    v[r] = (up == lower) ? mn : mx;
                }
            } else {
                int jr = j >> 5;
#pragma unroll
                for (int r = 0; r < 8; r++) {
                    if ((r & jr) == 0) {
                        int r2 = r | jr;
                        int idx = r * 32 + lane;
                        bool up = ((idx & k) == 0);
                        float mn = fminf(v[r], v[r2]), mx = fmaxf(v[r], v[r2]);
                        v[r] = up ? mn : mx;
                        v[r2] = up ? mx : mn;
                    }
                }
            }
        }
    }
    float* dst = g_pooled + (size_t)item * 192;
#pragma unroll
    for (int r = 0; r < 6; r++) dst[r * 32 + lane] = v[r];
}

// ---------------- CNN head: one block (128 thr) per graph -------------------
__global__ void k_cnn(const float* __restrict__ Wc1, const float* __restrict__ bc1,
                      const float* __restrict__ Wc2, const float* __restrict__ bc2,
                      const float* __restrict__ Wf,  const float* __restrict__ bf,
                      float* __restrict__ out_c, float* __restrict__ out_xf) {
    __shared__ float sp[10 * 192];   // pooled tile
    __shared__ float w1[32 * 40];    // Wc1
    __shared__ float w2[64 * 96];    // Wc2
    __shared__ float s1[32 * 48];
    __shared__ float s2[32 * 12];
    __shared__ float s3[64 * 4];
    __shared__ float sxf[64];
    int g = blockIdx.x, t = threadIdx.x;
    for (int i = t; i < 1920; i += 128) sp[i] = g_pooled[(size_t)g * 1920 + i];
    for (int i = t; i < 1280; i += 128) w1[i] = Wc1[i];
    for (int i = t; i < 6144; i += 128) w2[i] = Wc2[i];
    __syncthreads();
    // conv1 (C_in=10, k=4, stride=4) + relu -> [32,48]
    for (int idx = t; idx < 1536; idx += 128) {
        int o = idx / 48, p = idx % 48;
        float acc = bc1[o];
        const float* wr = &w1[o * 40];
        const float* in0 = &sp[p * 4];
#pragma unroll
        for (int i = 0; i < 10; i++)
#pragma unroll
            for (int q = 0; q < 4; q++)
                acc = fmaf(in0[i * 192 + q], wr[i * 4 + q], acc);
        s1[idx] = fmaxf(acc, 0.f);
    }
    __syncthreads();
    // maxpool 4/4 -> [32,12]
    for (int idx = t; idx < 384; idx += 128) {
        int o = idx / 12, p = idx % 12;
        const float* r0 = &s1[o * 48 + p * 4];
        s2[idx] = fmaxf(fmaxf(r0[0], r0[1]), fmaxf(r0[2], r0[3]));
    }
    __syncthreads();
    // conv2 (C_in=32, k=3, stride=3) + relu -> [64,4]
    for (int idx = t; idx < 256; idx += 128) {
        int o = idx / 4, p = idx % 4;
        float acc = bc2[o];
        const float* wr = &w2[o * 96];
#pragma unroll
        for (int i = 0; i < 32; i++)
#pragma unroll
            for (int q = 0; q < 3; q++)
                acc = fmaf(s2[i * 12 + p * 3 + q], wr[i * 3 + q], acc);
        s3[idx] = fmaxf(acc, 0.f);
    }
    __syncthreads();
    // maxpool 4 -> xf[64]
    if (t < 64) {
        float m = fmaxf(fmaxf(s3[t * 4], s3[t * 4 + 1]),
                        fmaxf(s3[t * 4 + 2], s3[t * 4 + 3]));
        sxf[t] = m;
        out_xf[(size_t)g * 64 + t] = m;
    }
    __syncthreads();
    // FC: c = relu(xf) @ Wf + bf
    if (t < 10) {
        float acc = bf[t];
#pragma unroll
        for (int o = 0; o < 64; o++)
            acc = fmaf(fmaxf(sxf[o], 0.f), Wf[o * 10 + t], acc);
        out_c[(size_t)g * 10 + t] = acc;
    }
}

// ---------------- launcher ----------------
extern "C" void kernel_launch(void* const* d_in, const int* in_sizes, int n_in,
                              void* d_out, int out_size) {
    const float* x   = (const float*)d_in[0];
    const int*   ei  = (const int*)d_in[1];
    // d_in[2] = batch (implicit: repeat(arange(B), 50))
    const float* W1  = (const float*)d_in[3];
    const float* b1  = (const float*)d_in[4];
    const float* W2  = (const float*)d_in[5];
    const float* b2  = (const float*)d_in[6];
    const float* W3  = (const float*)d_in[7];
    const float* b3  = (const float*)d_in[8];
    const float* Wc1 = (const float*)d_in[9];
    const float* bc1 = (const float*)d_in[10];
    const float* Wc2 = (const float*)d_in[11];
    const float* bc2 = (const float*)d_in[12];
    const float* Wf  = (const float*)d_in[13];
    const float* bf  = (const float*)d_in[14];
    float* out = (float*)d_out;
    float* out_c  = out;                 // [B,10]
    float* out_xf = out + (size_t)BB * 10; // [B,64]

    const int* row = ei;
    const int* col = ei + EE;

    // degree + CSR
    k_init<<<NN / 256, 256>>>();
    k_count<<<EE / 256, 256>>>(col);
    k_scan_blk<<<200, 1024>>>();
    k_scan_top<<<1, 256>>>();
    k_scan_add<<<200, 1024>>>();
    k_dinv<<<NN / 256, 256>>>();
    k_scatter<<<EE / 256, 256>>>(row, col);

    // layer 1: F_IN=128 input x (stride 128), output -> feat[:, 0:64]
    k_gemm<128><<<NN / 8, 256>>>(x, 128, 0, W1);
    k_agg<<<NN * 32 / 256, 256>>>(b1, 0);
    // layer 2: input feat[:, 0:64] (stride 192), output -> feat[:, 64:128]
    k_gemm<64><<<NN / 8, 256>>>((const float*)nullptr, 192, 0, W2);
    k_agg<<<NN * 32 / 256, 256>>>(b2, 64);
    // layer 3: input feat[:, 64:128], output -> feat[:, 128:192]
    k_gemm<64><<<NN / 8, 256>>>((const float*)nullptr, 192, 64, W3);
    k_agg<<<NN * 32 / 256, 256>>>(b3, 128);

    // sort-pooling
    k_maxkey<<<NN * 32 / 256, 256>>>();
    k_select<<<BB, 64>>>();
    k_sortfeat<<<BB * KTOP * 32 / 256, 256>>>();

    // CNN head + FC
    k_cnn<<<BB, 128>>>(Wc1, bc1, Wc2, bc2, Wf, bf, out_c, out_xf);
}

// round 9
// speedup vs baseline: 1.3394x; 1.3394x over previous
#include <cuda_runtime.h>

#define NN 204800
#define EE 1638400
#define BB 4096
#define KTOP 10
#define NPG 50

// ---------------- scratch (no allocation allowed) ----------------
__device__ float g_dinv[NN];
__device__ int   g_cnt[NN];
__device__ int   g_off[NN];
__device__ int   g_cur[NN];
__device__ int   g_bsum[200];
__device__ int2  g_edge[EE];                 // {src, coef bits}
__device__ float g_h[(size_t)NN * 64];       // GEMM output per layer
__device__ float g_feat[(size_t)NN * 192];   // x1 | x2 | x3 concat
__device__ float g_key[NN];                  // per-node max feature
__device__ int   g_sel[BB * KTOP];           // selected node per (graph, rank)
__device__ float g_pooled[(size_t)BB * KTOP * 192];

// ---------------- degree / CSR build ----------------
__global__ void k_init() {
    int i = blockIdx.x * 256 + threadIdx.x;
    g_cnt[i] = 0; g_cur[i] = 0;
}

__global__ void k_count(const int* __restrict__ col) {
    int e = blockIdx.x * 256 + threadIdx.x;
    atomicAdd(&g_cnt[col[e]], 1);
}

__global__ void k_scan_blk() {
    __shared__ int sh[1024];
    int t = threadIdx.x, i = blockIdx.x * 1024 + t;
    int v = g_cnt[i];
    sh[t] = v; __syncthreads();
    for (int d = 1; d < 1024; d <<= 1) {
        int a = (t >= d) ? sh[t - d] : 0; __syncthreads();
        sh[t] += a; __syncthreads();
    }
    g_off[i] = sh[t] - v;                 // exclusive within block
    if (t == 1023) g_bsum[blockIdx.x] = sh[1023];
}

__global__ void k_scan_top() {
    __shared__ int sh[256];
    int t = threadIdx.x;
    int v = (t < 200) ? g_bsum[t] : 0;
    sh[t] = v; __syncthreads();
    for (int d = 1; d < 256; d <<= 1) {
        int a = (t >= d) ? sh[t - d] : 0; __syncthreads();
        sh[t] += a; __syncthreads();
    }
    if (t < 200) g_bsum[t] = sh[t] - v;   // exclusive block sums
}

__global__ void k_scan_add() {
    int i = blockIdx.x * 1024 + threadIdx.x;
    g_off[i] += g_bsum[blockIdx.x];
}

__global__ void k_dinv() {
    int i = blockIdx.x * 256 + threadIdx.x;
    g_dinv[i] = rsqrtf((float)g_cnt[i] + 1.0f);
}

__global__ void k_scatter(const int* __restrict__ row, const int* __restrict__ col) {
    int e = blockIdx.x * 256 + threadIdx.x;
    int c = col[e], r = row[e];
    int pos = g_off[c] + atomicAdd(&g_cur[c], 1);
    g_edge[pos] = make_int2(r, __float_as_int(g_dinv[r] * g_dinv[c]));
}

// ---------------- packed f32x2 FMA ----------------
__device__ __forceinline__ float2 ffma2(float2 a, float2 b, float2 c) {
    float2 d;
    asm("fma.rn.f32x2 %0, %1, %2, %3;"
        : "=l"(*(unsigned long long*)&d)
        : "l"(*(unsigned long long*)&a),
          "l"(*(unsigned long long*)&b),
          "l"(*(unsigned long long*)&c));
    return d;
}

// ---------------- GEMM: h = in @ W ----------------
// block = 256 thr computes 32 rows x 64 cols.
// x tile stored TRANSPOSED in shared (xs[k][row]); accumulators pack ROW pairs
// into f32x2, so each FFMA2 covers 2 rows x 64 lanescols.
template<int KDIM>
__global__ void k_gemm(const float* __restrict__ xin, int instride, int inoff,
                       const float* __restrict__ W) {
    __shared__ float Ws[KDIM * 64];
    __shared__ float xs[KDIM * 32];
    int t = threadIdx.x;
    int w = t >> 5, lane = t & 31;
    for (int i = t; i < KDIM * 64; i += 256) Ws[i] = W[i];
    const float* base = xin ? xin : (const float*)g_feat;
    int row0 = blockIdx.x * 32;
    // transposed x load: lane = row -> STS conflict-free (bank = lane)
    for (int q = w; q < KDIM / 4; q += 8) {
        float4 v = *(const float4*)&base[(size_t)(row0 + lane) * instride + inoff + q * 4];
        xs[(q * 4 + 0) * 32 + lane] = v.x;
        xs[(q * 4 + 1) * 32 + lane] = v.y;
        xs[(q * 4 + 2) * 32 + lane] = v.z;
        xs[(q * 4 + 3) * 32 + lane] = v.w;
    }
    __syncthreads();
    float2 acc00 = make_float2(0.f, 0.f), acc01 = acc00, acc10 = acc00, acc11 = acc00;
    int r = w * 4;   // this warp's 4 rows within tile
#pragma unroll 4
    for (int k = 0; k < KDIM; k++) {
        float2 wv = *(const float2*)&Ws[k * 64 + lane * 2];   // cols 2l,2l+1
        float4 xq = *(const float4*)&xs[k * 32 + r];          // rows r..r+3 (broadcast)
        float2 W0 = make_float2(wv.x, wv.x);
        float2 W1 = make_float2(wv.y, wv.y);
        float2 p0 = make_float2(xq.x, xq.y);                  // rows r, r+1
        float2 p1 = make_float2(xq.z, xq.w);                  // rows r+2, r+3
        acc00 = ffma2(p0, W0, acc00);
        acc01 = ffma2(p0, W1, acc01);
        acc10 = ffma2(p1, W0, acc10);
        acc11 = ffma2(p1, W1, acc11);
    }
    size_t rb = (size_t)(row0 + r) * 64 + lane * 2;
    *(float2*)&g_h[rb]           = make_float2(acc00.x, acc01.x);  // row r
    *(float2*)&g_h[rb + 64]      = make_float2(acc00.y, acc01.y);  // row r+1
    *(float2*)&g_h[rb + 128]     = make_float2(acc10.x, acc11.x);  // row r+2
    *(float2*)&g_h[rb + 192]     = make_float2(acc10.y, acc11.y);  // row r+3
}

// ---------------- aggregation: one warp per target node, MLP=8 gather ------
__global__ void k_agg(const float* __restrict__ bias, int outoff) {
    int n = (blockIdx.x * 256 + threadIdx.x) >> 5;
    int lane = threadIdx.x & 31;
    float di = g_dinv[n];
    float s = di * di;
    float2 hv = *(const float2*)&g_h[(size_t)n * 64 + lane * 2];
    float a0 = hv.x * s, a1 = hv.y * s;
    int beg = g_off[n], deg = g_cnt[n];
    for (int bb = 0; bb < deg; bb += 32) {
        int rem = deg - bb;
        int cnt = rem < 32 ? rem : 32;
        int2 ed = (lane < cnt) ? g_edge[beg + bb + lane] : make_int2(n, 0);
        int se = ed.x;
        float ce = __int_as_float(ed.y);
        for (int i = 0; i < cnt; i += 8) {
            int   sj[8];
            float cj[8];
#pragma unroll
            for (int j = 0; j < 8; j++) {
                int idx = i + j;
                sj[j] = __shfl_sync(0xffffffffu, se, idx & 31);
                float c = __shfl_sync(0xffffffffu, ce, idx & 31);
                cj[j] = (idx < cnt) ? c : 0.f;
            }
            float2 v[8];
#pragma unroll
            for (int j = 0; j < 8; j++)
                v[j] = *(const float2*)&g_h[(size_t)sj[j] * 64 + lane * 2];
#pragma unroll
            for (int j = 0; j < 8; j++) {
                a0 = fmaf(v[j].x, cj[j], a0);
                a1 = fmaf(v[j].y, cj[j], a1);
            }
        }
    }
    float t0 = tanhf(a0 + bias[lane * 2]);
    float t1 = tanhf(a1 + bias[lane * 2 + 1]);
    *(float2*)&g_feat[(size_t)n * 192 + outoff + lane * 2] = make_float2(t0, t1);
}

// ---------------- per-node max over 192 features (sort-pool key) ------------
__global__ void k_maxkey() {
    int n = (blockIdx.x * 256 + threadIdx.x) >> 5;
    int lane = threadIdx.x & 31;
    const float* f = g_feat + (size_t)n * 192;
    float m = -3.4e38f;
#pragma unroll
    for (int r = 0; r < 6; r++) m = fmaxf(m, f[r * 32 + lane]);
#pragma unroll
    for (int d = 16; d > 0; d >>= 1) m = fmaxf(m, __shfl_xor_sync(0xffffffffu, m, d));
    if (lane == 0) g_key[n] = m;
}

// ---------------- per-graph top-K selection (key desc, tie: index asc) ------
__global__ void k_select() {
    __shared__ float sk[NPG];
    int g = blockIdx.x, t = threadIdx.x;
    if (t < NPG) sk[t] = g_key[g * NPG + t];
    __syncthreads();
    if (t < NPG) {
        float kv = sk[t];
        int r = 0;
        for (int j = 0; j < NPG; j++) {
            float kj = sk[j];
            r += (int)((kj > kv) || ((kj == kv) && (j < t)));
        }
        if (r < KTOP) g_sel[g * KTOP + r] = g * NPG + t;
    }
}

// ---------------- sort 192 features ascending for selected nodes ------------
__global__ void k_sortfeat() {
    int item = (blockIdx.x * 256 + threadIdx.x) >> 5;
    int lane = threadIdx.x & 31;
    int node = g_sel[item];
    const float* f = g_feat + (size_t)node * 192;
    const float INF = __int_as_float(0x7f800000);
    float v[8];
#pragma unroll
    for (int r = 0; r < 8; r++) {
        int idx = r * 32 + lane;
        v[r] = (idx < 192) ? f[idx] : INF;
    }
#pragma unroll
    for (int k = 2; k <= 256; k <<= 1) {
#pragma unroll
        for (int j = 128; j > 0; j >>= 1) {
            if (j >= k) continue;
            if (j < 32) {
#pragma unroll
                for (int r = 0; r < 8; r++) {
                    int idx = r * 32 + lane;
                    float o = __shfl_xor_sync(0xffffffffu, v[r], j);
                    bool up = ((idx & k) == 0);
                    bool lower = ((lane & j) == 0);
                    float mn = fminf(v[r], o), mx = fmaxf(v[r], o);
                    v[r] = (up == lower) ? mn : mx;
                }
            } else {
                int jr = j >> 5;
#pragma unroll
                for (int r = 0; r < 8; r++) {
                    if ((r & jr) == 0) {
                        int r2 = r | jr;
                        int idx = r * 32 + lane;
                        bool up = ((idx & k) == 0);
                        float mn = fminf(v[r], v[r2]), mx = fmaxf(v[r], v[r2]);
                        v[r] = up ? mn : mx;
                        v[r2] = up ? mx : mn;
                    }
                }
            }
        }
    }
    float* dst = g_pooled + (size_t)item * 192;
#pragma unroll
    for (int r = 0; r < 6; r++) dst[r * 32 + lane] = v[r];
}

// ---------------- CNN head: one block (128 thr) per graph -------------------
__global__ void k_cnn(const float* __restrict__ Wc1, const float* __restrict__ bc1,
                      const float* __restrict__ Wc2, const float* __restrict__ bc2,
                      const float* __restrict__ Wf,  const float* __restrict__ bf,
                      float* __restrict__ out_c, float* __restrict__ out_xf) {
    __shared__ float sp[10 * 192];   // pooled tile
    __shared__ float w1[32 * 40];    // Wc1
    __shared__ float w2[64 * 96];    // Wc2
    __shared__ float s1[32 * 48];
    __shared__ float s2[32 * 12];
    __shared__ float s3[64 * 4];
    __shared__ float sxf[64];
    int g = blockIdx.x, t = threadIdx.x;
    for (int i = t; i < 1920; i += 128) sp[i] = g_pooled[(size_t)g * 1920 + i];
    for (int i = t; i < 1280; i += 128) w1[i] = Wc1[i];
    for (int i = t; i < 6144; i += 128) w2[i] = Wc2[i];
    __syncthreads();
    // conv1 (C_in=10, k=4, stride=4) + relu -> [32,48]
    for (int idx = t; idx < 1536; idx += 128) {
        int o = idx / 48, p = idx % 48;
        float acc = bc1[o];
        const float* wr = &w1[o * 40];
        const float* in0 = &sp[p * 4];
#pragma unroll
        for (int i = 0; i < 10; i++)
#pragma unroll
            for (int q = 0; q < 4; q++)
                acc = fmaf(in0[i * 192 + q], wr[i * 4 + q], acc);
        s1[idx] = fmaxf(acc, 0.f);
    }
    __syncthreads();
    // maxpool 4/4 -> [32,12]
    for (int idx = t; idx < 384; idx += 128) {
        int o = idx / 12, p = idx % 12;
        const float* r0 = &s1[o * 48 + p * 4];
        s2[idx] = fmaxf(fmaxf(r0[0], r0[1]), fmaxf(r0[2], r0[3]));
    }
    __syncthreads();
    // conv2 (C_in=32, k=3, stride=3) + relu -> [64,4]
    for (int idx = t; idx < 256; idx += 128) {
        int o = idx / 4, p = idx % 4;
        float acc = bc2[o];
        const float* wr = &w2[o * 96];
#pragma unroll
        for (int i = 0; i < 32; i++)
#pragma unroll
            for (int q = 0; q < 3; q++)
                acc = fmaf(s2[i * 12 + p * 3 + q], wr[i * 3 + q], acc);
        s3[idx] = fmaxf(acc, 0.f);
    }
    __syncthreads();
    // maxpool 4 -> xf[64]
    if (t < 64) {
        float m = fmaxf(fmaxf(s3[t * 4], s3[t * 4 + 1]),
                        fmaxf(s3[t * 4 + 2], s3[t * 4 + 3]));
        sxf[t] = m;
        out_xf[(size_t)g * 64 + t] = m;
    }
    __syncthreads();
    // FC: c = relu(xf) @ Wf + bf
    if (t < 10) {
        float acc = bf[t];
#pragma unroll
        for (int o = 0; o < 64; o++)
            acc = fmaf(fmaxf(sxf[o], 0.f), Wf[o * 10 + t], acc);
        out_c[(size_t)g * 10 + t] = acc;
    }
}

// ---------------- launcher ----------------
extern "C" void kernel_launch(void* const* d_in, const int* in_sizes, int n_in,
                              void* d_out, int out_size) {
    const float* x   = (const float*)d_in[0];
    const int*   ei  = (const int*)d_in[1];
    // d_in[2] = batch (implicit: repeat(arange(B), 50))
    const float* W1  = (const float*)d_in[3];
    const float* b1  = (const float*)d_in[4];
    const float* W2  = (const float*)d_in[5];
    const float* b2  = (const float*)d_in[6];
    const float* W3  = (const float*)d_in[7];
    const float* b3  = (const float*)d_in[8];
    const float* Wc1 = (const float*)d_in[9];
    const float* bc1 = (const float*)d_in[10];
    const float* Wc2 = (const float*)d_in[11];
    const float* bc2 = (const float*)d_in[12];
    const float* Wf  = (const float*)d_in[13];
    const float* bf  = (const float*)d_in[14];
    float* out = (float*)d_out;
    float* out_c  = out;                   // [B,10]
    float* out_xf = out + (size_t)BB * 10; // [B,64]

    const int* row = ei;
    const int* col = ei + EE;

    // degree + CSR
    k_init<<<NN / 256, 256>>>();
    k_count<<<EE / 256, 256>>>(col);
    k_scan_blk<<<200, 1024>>>();
    k_scan_top<<<1, 256>>>();
    k_scan_add<<<200, 1024>>>();
    k_dinv<<<NN / 256, 256>>>();
    k_scatter<<<EE / 256, 256>>>(row, col);

    // layer 1: F_IN=128 input x (stride 128), output -> feat[:, 0:64]
    k_gemm<128><<<NN / 32, 256>>>(x, 128, 0, W1);
    k_agg<<<NN * 32 / 256, 256>>>(b1, 0);
    // layer 2: input feat[:, 0:64] (stride 192), output -> feat[:, 64:128]
    k_gemm<64><<<NN / 32, 256>>>((const float*)nullptr, 192, 0, W2);
    k_agg<<<NN * 32 / 256, 256>>>(b2, 64);
    // layer 3: input feat[:, 64:128], output -> feat[:, 128:192]
    k_gemm<64><<<NN / 32, 256>>>((const float*)nullptr, 192, 64, W3);
    k_agg<<<NN * 32 / 256, 256>>>(b3, 128);

    // sort-pooling
    k_maxkey<<<NN * 32 / 256, 256>>>();
    k_select<<<BB, 64>>>();
    k_sortfeat<<<BB * KTOP * 32 / 256, 256>>>();

    // CNN head + FC
    k_cnn<<<BB, 128>>>(Wc1, bc1, Wc2, bc2, Wf, bf, out_c, out_xf);
}

// round 10
// speedup vs baseline: 1.7268x; 1.2892x over previous
#include <cuda_runtime.h>

#define NN 204800
#define EE 1638400
#define BB 4096
#define KTOP 10
#define NPG 50

// ---------------- scratch (no allocation allowed) ----------------
__device__ float g_dinv[NN];
__device__ int   g_cnt[NN];
__device__ int   g_off[NN];
__device__ int   g_cur[NN];
__device__ int   g_bsum[200];
__device__ int2  g_edge[EE];                 // {src, coef bits}
__device__ float g_h[(size_t)NN * 64];       // GEMM output per layer
__device__ float g_feat[(size_t)NN * 192];   // x1 | x2 | x3 concat
__device__ float g_key[NN];                  // per-node max feature

// ---------------- degree / CSR build ----------------
__global__ void k_init() {
    int i = blockIdx.x * 256 + threadIdx.x;
    g_cnt[i] = 0;
}

__global__ void k_count(const int* __restrict__ col) {
    int e = blockIdx.x * 256 + threadIdx.x;
    atomicAdd(&g_cnt[col[e]], 1);
}

__global__ void k_scan_blk() {
    __shared__ int sh[1024];
    int t = threadIdx.x, i = blockIdx.x * 1024 + t;
    int v = g_cnt[i];
    g_dinv[i] = rsqrtf((float)v + 1.0f);   // fused: dinv from raw degree
    g_cur[i] = 0;                          // fused: scatter cursor init
    sh[t] = v; __syncthreads();
    for (int d = 1; d < 1024; d <<= 1) {
        int a = (t >= d) ? sh[t - d] : 0; __syncthreads();
        sh[t] += a; __syncthreads();
    }
    g_off[i] = sh[t] - v;                 // exclusive within block
    if (t == 1023) g_bsum[blockIdx.x] = sh[1023];
}

__global__ void k_scan_top() {
    __shared__ int sh[256];
    int t = threadIdx.x;
    int v = (t < 200) ? g_bsum[t] : 0;
    sh[t] = v; __syncthreads();
    for (int d = 1; d < 256; d <<= 1) {
        int a = (t >= d) ? sh[t - d] : 0; __syncthreads();
        sh[t] += a; __syncthreads();
    }
    if (t < 200) g_bsum[t] = sh[t] - v;   // exclusive block sums
}

__global__ void k_scan_add() {
    int i = blockIdx.x * 1024 + threadIdx.x;
    g_off[i] += g_bsum[blockIdx.x];
}

__global__ void k_scatter(const int* __restrict__ row, const int* __restrict__ col) {
    int e = blockIdx.x * 256 + threadIdx.x;
    int c = col[e], r = row[e];
    int pos = g_off[c] + atomicAdd(&g_cur[c], 1);
    g_edge[pos] = make_int2(r, __float_as_int(g_dinv[r] * g_dinv[c]));
}

// ---------------- packed f32x2 FMA ----------------
__device__ __forceinline__ float2 ffma2(float2 a, float2 b, float2 c) {
    float2 d;
    asm("fma.rn.f32x2 %0, %1, %2, %3;"
        : "=l"(*(unsigned long long*)&d)
        : "l"(*(unsigned long long*)&a),
          "l"(*(unsigned long long*)&b),
          "l"(*(unsigned long long*)&c));
    return d;
}

// ---------------- GEMM: h = in @ W ----------------
// block = 256 thr computes 128 rows x 64 cols; 16 rows per warp.
// x staged transposed in shared 16 k at a time (conflict-free both ways);
// accumulators pack ROW pairs into f32x2: 23 issues per k per 16 rows.
template<int KDIM>
__global__ void k_gemm(const float* __restrict__ xin, int instride, int inoff,
                       const float* __restrict__ W) {
    __shared__ float Ws[KDIM * 64];
    __shared__ float xs[16 * 128];
    int t = threadIdx.x;
    int w = t >> 5, lane = t & 31;
    for (int i = t; i < KDIM * 64; i += 256) Ws[i] = W[i];
    const float* base = xin ? xin : (const float*)g_feat;
    int row0 = blockIdx.x * 128;
    int r = w * 16;                        // warp's first row in tile
    int rr = t & 127;                      // staging row
    int kq0 = (t >> 7) * 2;                // staging float4-col base (0 or 2)
    const float* xrow = base + (size_t)(row0 + rr) * instride + inoff;
    float2 acc[8][2];
#pragma unroll
    for (int i = 0; i < 8; i++) { acc[i][0] = make_float2(0.f, 0.f); acc[i][1] = acc[i][0]; }
    for (int kb = 0; kb < KDIM; kb += 16) {
        __syncthreads();
#pragma unroll
        for (int j = 0; j < 2; j++) {
            int kq = kq0 + j;
            float4 v = *(const float4*)&xrow[kb + kq * 4];
            xs[(kq * 4 + 0) * 128 + rr] = v.x;
            xs[(kq * 4 + 1) * 128 + rr] = v.y;
            xs[(kq * 4 + 2) * 128 + rr] = v.z;
            xs[(kq * 4 + 3) * 128 + rr] = v.w;
        }
        __syncthreads();
#pragma unroll
        for (int k = 0; k < 16; k++) {
            float2 wv = *(const float2*)&Ws[(kb + k) * 64 + lane * 2];
            float2 W0 = make_float2(wv.x, wv.x);
            float2 W1 = make_float2(wv.y, wv.y);
            const float4* xp = (const float4*)&xs[k * 128 + r];
            float4 xa = xp[0], xb = xp[1], xc = xp[2], xd = xp[3];
            float2 p;
            p = make_float2(xa.x, xa.y);
            acc[0][0] = ffma2(p, W0, acc[0][0]); acc[0][1] = ffma2(p, W1, acc[0][1]);
            p = make_float2(xa.z, xa.w);
            acc[1][0] = ffma2(p, W0, acc[1][0]); acc[1][1] = ffma2(p, W1, acc[1][1]);
            p = make_float2(xb.x, xb.y);
            acc[2][0] = ffma2(p, W0, acc[2][0]); acc[2][1] = ffma2(p, W1, acc[2][1]);
            p = make_float2(xb.z, xb.w);
            acc[3][0] = ffma2(p, W0, acc[3][0]); acc[3][1] = ffma2(p, W1, acc[3][1]);
            p = make_float2(xc.x, xc.y);
            acc[4][0] = ffma2(p, W0, acc[4][0]); acc[4][1] = ffma2(p, W1, acc[4][1]);
            p = make_float2(xc.z, xc.w);
            acc[5][0] = ffma2(p, W0, acc[5][0]); acc[5][1] = ffma2(p, W1, acc[5][1]);
            p = make_float2(xd.x, xd.y);
            acc[6][0] = ffma2(p, W0, acc[6][0]); acc[6][1] = ffma2(p, W1, acc[6][1]);
            p = make_float2(xd.z, xd.w);
            acc[7][0] = ffma2(p, W0, acc[7][0]); acc[7][1] = ffma2(p, W1, acc[7][1]);
        }
    }
#pragma unroll
    for (int i = 0; i < 8; i++) {
        size_t rb = (size_t)(row0 + r + 2 * i) * 64 + lane * 2;
        *(float2*)&g_h[rb]      = make_float2(acc[i][0].x, acc[i][1].x);
        *(float2*)&g_h[rb + 64] = make_float2(acc[i][0].y, acc[i][1].y);
    }
}

// ---------------- aggregation: one warp per target node, MLP=8 gather ------
// fused: also maintains per-node max over the produced feature slice (sort key)
__global__ void k_agg(const float* __restrict__ bias, int outoff, int first) {
    int n = (blockIdx.x * 256 + threadIdx.x) >> 5;
    int lane = threadIdx.x & 31;
    float di = g_dinv[n];
    float s = di * di;
    float2 hv = *(const float2*)&g_h[(size_t)n * 64 + lane * 2];
    float a0 = hv.x * s, a1 = hv.y * s;
    int beg = g_off[n], deg = g_cnt[n];
    for (int bb = 0; bb < deg; bb += 32) {
        int rem = deg - bb;
        int cnt = rem < 32 ? rem : 32;
        int2 ed = (lane < cnt) ? g_edge[beg + bb + lane] : make_int2(n, 0);
        int se = ed.x;
        float ce = __int_as_float(ed.y);
        for (int i = 0; i < cnt; i += 8) {
            int   sj[8];
            float cj[8];
#pragma unroll
            for (int j = 0; j < 8; j++) {
                int idx = i + j;
                sj[j] = __shfl_sync(0xffffffffu, se, idx & 31);
                float c = __shfl_sync(0xffffffffu, ce, idx & 31);
                cj[j] = (idx < cnt) ? c : 0.f;
            }
            float2 v[8];
#pragma unroll
            for (int j = 0; j < 8; j++)
                v[j] = *(const float2*)&g_h[(size_t)sj[j] * 64 + lane * 2];
#pragma unroll
            for (int j = 0; j < 8; j++) {
                a0 = fmaf(v[j].x, cj[j], a0);
                a1 = fmaf(v[j].y, cj[j], a1);
            }
        }
    }
    float t0 = tanhf(a0 + bias[lane * 2]);
    float t1 = tanhf(a1 + bias[lane * 2 + 1]);
    *(float2*)&g_feat[(size_t)n * 192 + outoff + lane * 2] = make_float2(t0, t1);
    // running sort-key max
    float m = fmaxf(t0, t1);
#pragma unroll
    for (int d = 16; d > 0; d >>= 1) m = fmaxf(m, __shfl_xor_sync(0xffffffffu, m, d));
    if (lane == 0) g_key[n] = first ? m : fmaxf(g_key[n], m);
}

// ---------------- fused head: select + sort + conv1/pool/conv2/pool + FC ----
// one block (320 thr = 10 warps) per graph.
__global__ __launch_bounds__(320, 4)
void k_cnn(const float* __restrict__ Wc1, const float* __restrict__ bc1,
           const float* __restrict__ Wc2, const float* __restrict__ bc2,
           const float* __restrict__ Wf,  const float* __restrict__ bf,
           float* __restrict__ out_c, float* __restrict__ out_xf) {
    __shared__ float sp[10 * 192];   // sorted pooled tile (channel-major)
    __shared__ float w1[32 * 40];
    __shared__ float w2[64 * 96];
    __shared__ float s1[32 * 48];
    __shared__ float s2[32 * 12];
    __shared__ float s3[64 * 4];
    __shared__ float sxf[64];
    __shared__ float sk[64];
    __shared__ int   sel[16];
    int g = blockIdx.x, t = threadIdx.x;
    int w = t >> 5, lane = t & 31;

    if (t < NPG) sk[t] = g_key[g * NPG + t];
    for (int i = t; i < 1280; i += 320) w1[i] = Wc1[i];
    for (int i = t; i < 6144; i += 320) w2[i] = Wc2[i];
    __syncthreads();

    // top-K selection (key desc, tie: index asc) — ranks are a permutation
    if (t < NPG) {
        float kv = sk[t];
        int r = 0;
        for (int j = 0; j < NPG; j++) {
            float kj = sk[j];
            r += (int)((kj > kv) || ((kj == kv) && (j < t)));
        }
        if (r < KTOP) sel[r] = g * NPG + t;
    }
    __syncthreads();

    // warps 0..9: sort own selected node's 192 feats ascending (bitonic-256)
    if (w < KTOP) {
        int node = sel[w];
        const float* f = g_feat + (size_t)node * 192;
        const float INF = __int_as_float(0x7f800000);
        float v[8];
#pragma unroll
        for (int r = 0; r < 8; r++) {
            int idx = r * 32 + lane;
            v[r] = (idx < 192) ? f[idx] : INF;
        }
#pragma unroll
        for (int k = 2; k <= 256; k <<= 1) {
#pragma unroll
            for (int j = 128; j > 0; j >>= 1) {
                if (j >= k) continue;
                if (j < 32) {
#pragma unroll
                    for (int r = 0; r < 8; r++) {
                        int idx = r * 32 + lane;
                        float o = __shfl_xor_sync(0xffffffffu, v[r], j);
                        bool up = ((idx & k) == 0);
                        bool lower = ((lane & j) == 0);
                        float mn = fminf(v[r], o), mx = fmaxf(v[r], o);
                        v[r] = (up == lower) ? mn : mx;
                    }
                } else {
                    int jr = j >> 5;
#pragma unroll
                    for (int r = 0; r < 8; r++) {
                        if ((r & jr) == 0) {
                            int r2 = r | jr;
                            int idx = r * 32 + lane;
                            bool up = ((idx & k) == 0);
                            float mn = fminf(v[r], v[r2]), mx = fmaxf(v[r], v[r2]);
                            v[r] = up ? mn : mx;
                            v[r2] = up ? mx : mn;
                        }
                    }
                }
            }
        }
#pragma unroll
        for (int r = 0; r < 6; r++) sp[w * 192 + r * 32 + lane] = v[r];
    }
    __syncthreads();

    // conv1 (C_in=10, k=4, stride=4) + relu -> s1[32][48]
    // warp w<8 owns channels o = 4w..4w+3 (weights warp-uniform -> LDS broadcast)
    if (w < 8) {
        const float4* sp4 = (const float4*)sp;   // [i][48] float4 positions
#pragma unroll
        for (int oo = 0; oo < 4; oo++) {
            int o = w * 4 + oo;
            const float4* w4 = (const float4*)&w1[o * 40];
            float a0 = bc1[o], a1 = a0;
#pragma unroll
            for (int i = 0; i < 10; i++) {
                float4 wv = w4[i];
                float4 xa = sp4[i * 48 + lane];
                a0 = fmaf(xa.x, wv.x, a0); a0 = fmaf(xa.y, wv.y, a0);
                a0 = fmaf(xa.z, wv.z, a0); a0 = fmaf(xa.w, wv.w, a0);
                if (lane < 16) {
                    float4 xb = sp4[i * 48 + 32 + lane];
                    a1 = fmaf(xb.x, wv.x, a1); a1 = fmaf(xb.y, wv.y, a1);
                    a1 = fmaf(xb.z, wv.z, a1); a1 = fmaf(xb.w, wv.w, a1);
                }
            }
            s1[o * 48 + lane] = fmaxf(a0, 0.f);
            if (lane < 16) s1[o * 48 + 32 + lane] = fmaxf(a1, 0.f);
        }
    }
    __syncthreads();

    // maxpool 4/4 -> s2[32][12]
    for (int idx = t; idx < 384; idx += 320) {
        int o = idx / 12, p = idx % 12;
        const float* r0 = &s1[o * 48 + p * 4];
        s2[idx] = fmaxf(fmaxf(r0[0], r0[1]), fmaxf(r0[2], r0[3]));
    }
    __syncthreads();

    // conv2 (C_in=32, k=3, stride=3) + relu -> s3[64][4]
    // warp w<8 owns channels o = 8w..8w+7; lane = (ipart, p); shfl-reduce ipart
    if (w < 8) {
        int p = lane & 3, ipart = lane >> 2;
#pragma unroll
        for (int j = 0; j < 8; j++) {
            int o = w * 8 + j;
            float acc = 0.f;
#pragma unroll
            for (int m = 0; m < 4; m++) {
                int i = ipart + m * 8;
                const float* s2r = &s2[i * 12 + p * 3];
                const float* w2r = &w2[o * 96 + i * 3];
                acc = fmaf(s2r[0], w2r[0], acc);
                acc = fmaf(s2r[1], w2r[1], acc);
                acc = fmaf(s2r[2], w2r[2], acc);
            }
            acc += __shfl_xor_sync(0xffffffffu, acc, 4);
            acc += __shfl_xor_sync(0xffffffffu, acc, 8);
            acc += __shfl_xor_sync(0xffffffffu, acc, 16);
            if (lane < 4) s3[o * 4 + p] = fmaxf(acc + bc2[o], 0.f);
        }
    }
    __syncthreads();

    // maxpool 4 -> xf[64]
    if (t < 64) {
        float m = fmaxf(fmaxf(s3[t * 4], s3[t * 4 + 1]),
                        fmaxf(s3[t * 4 + 2], s3[t * 4 + 3]));
        sxf[t] = m;
        out_xf[(size_t)g * 64 + t] = m;
    }
    __syncthreads();

    // FC: c = relu(xf) @ Wf + bf
    if (t < 10) {
        float acc = bf[t];
#pragma unroll
        for (int o = 0; o < 64; o++)
            acc = fmaf(fmaxf(sxf[o], 0.f), Wf[o * 10 + t], acc);
        out_c[(size_t)g * 10 + t] = acc;
    }
}

// ---------------- launcher ----------------
extern "C" void kernel_launch(void* const* d_in, const int* in_sizes, int n_in,
                              void* d_out, int out_size) {
    const float* x   = (const float*)d_in[0];
    const int*   ei  = (const int*)d_in[1];
    // d_in[2] = batch (implicit: repeat(arange(B), 50))
    const float* W1  = (const float*)d_in[3];
    const float* b1  = (const float*)d_in[4];
    const float* W2  = (const float*)d_in[5];
    const float* b2  = (const float*)d_in[6];
    const float* W3  = (const float*)d_in[7];
    const float* b3  = (const float*)d_in[8];
    const float* Wc1 = (const float*)d_in[9];
    const float* bc1 = (const float*)d_in[10];
    const float* Wc2 = (const float*)d_in[11];
    const float* bc2 = (const float*)d_in[12];
    const float* Wf  = (const float*)d_in[13];
    const float* bf  = (const float*)d_in[14];
    float* out = (float*)d_out;
    float* out_c  = out;                   // [B,10]
    float* out_xf = out + (size_t)BB * 10; // [B,64]

    const int* row = ei;
    const int* col = ei + EE;

    // degree + CSR
    k_init<<<NN / 256, 256>>>();
    k_count<<<EE / 256, 256>>>(col);
    k_scan_blk<<<200, 1024>>>();          // also: dinv + cursor init
    k_scan_top<<<1, 256>>>();
    k_scan_add<<<200, 1024>>>();
    k_scatter<<<EE / 256, 256>>>(row, col);

    // layer 1: F_IN=128 input x (stride 128), output -> feat[:, 0:64]
    k_gemm<128><<<NN / 128, 256>>>(x, 128, 0, W1);
    k_agg<<<NN * 32 / 256, 256>>>(b1, 0, 1);
    // layer 2: input feat[:, 0:64] (stride 192), output -> feat[:, 64:128]
    k_gemm<64><<<NN / 128, 256>>>((const float*)nullptr, 192, 0, W2);
    k_agg<<<NN * 32 / 256, 256>>>(b2, 64, 0);
    // layer 3: input feat[:, 64:128], output -> feat[:, 128:192]
    k_gemm<64><<<NN / 128, 256>>>((const float*)nullptr, 192, 64, W3);
    k_agg<<<NN * 32 / 256, 256>>>(b3, 128, 0);

    // fused select + sort + CNN head + FC
    k_cnn<<<BB, 320>>>(Wc1, bc1, Wc2, bc2, Wf, bf, out_c, out_xf);
}